// round 9
// baseline (speedup 1.0000x reference)
#include <cuda_runtime.h>
#include <cuda_fp16.h>
#include <cstdint>

#define N_TOK  12288
#define TILE   128
#define NTILE  96
#define NSPLIT 3
#define TPC    32          // j-tiles per CTA (NTILE / NSPLIT)
#define PSTR   136         // half-element stride of P/V smem rows (272 B)
#define PSCALE 0.7f
#define PVB    34816       // bytes per P/V tile buffer (128 * 136 * 2)

// smem byte offsets
#define SM_P    0           // 2 buffers
#define SM_V    69632       // 2 buffers
#define SM_RS   139264      // 128 floats
#define SMEM_TOTAL 139776

// ---------------- scratch (static device globals) ----------------
__device__ __half g_xt[(size_t)N_TOK * 128];            // x_tan fp16 [N, D]
__device__ float  g_e1[N_TOK];                          // 0.7*exp(wh1)
__device__ float  g_e1p[N_TOK];                         // 0.7*exp(0.2*wh1)
__device__ float  g_e2[N_TOK];                          // exp(wh2)
__device__ float  g_e2p[N_TOK];                         // exp(0.2*wh2)
__device__ float  g_pc[(size_t)NSPLIT * NTILE * TILE * 128];  // partial C, 18.9 MB
__device__ float  g_prs[(size_t)NSPLIT * N_TOK];              // partial rowsums

// ---------------- PTX helpers ----------------
__device__ __forceinline__ uint32_t smem_u32(const void* p) {
    return (uint32_t)__cvta_generic_to_shared(p);
}
__device__ __forceinline__ void ldsm_x4(uint32_t addr, uint32_t& r0, uint32_t& r1,
                                        uint32_t& r2, uint32_t& r3) {
    asm volatile("ldmatrix.sync.aligned.m8n8.x4.shared.b16 {%0,%1,%2,%3}, [%4];"
                 : "=r"(r0), "=r"(r1), "=r"(r2), "=r"(r3) : "r"(addr));
}
__device__ __forceinline__ void ldsm_x4_t(uint32_t addr, uint32_t& r0, uint32_t& r1,
                                          uint32_t& r2, uint32_t& r3) {
    asm volatile("ldmatrix.sync.aligned.m8n8.x4.trans.shared.b16 {%0,%1,%2,%3}, [%4];"
                 : "=r"(r0), "=r"(r1), "=r"(r2), "=r"(r3) : "r"(addr));
}
__device__ __forceinline__ void mma16816(float* c, const uint32_t* a, const uint32_t* b) {
    asm volatile("mma.sync.aligned.m16n8k16.row.col.f32.f16.f16.f32 "
                 "{%0,%1,%2,%3}, {%4,%5,%6,%7}, {%8,%9}, {%0,%1,%2,%3};"
                 : "+f"(c[0]), "+f"(c[1]), "+f"(c[2]), "+f"(c[3])
                 : "r"(a[0]), "r"(a[1]), "r"(a[2]), "r"(a[3]), "r"(b[0]), "r"(b[1]));
}

// ---------------- prep: logmap0 + wh exp factors + fp16 x_tan ----------------
__global__ __launch_bounds__(256) void prep_kernel(const float* __restrict__ x,
                                                   const float* __restrict__ a) {
    int gw   = (blockIdx.x * blockDim.x + threadIdx.x) >> 5;
    int lane = threadIdx.x & 31;
    if (gw >= N_TOK) return;

    const float4 xv = ((const float4*)(x + (size_t)gw * 128))[lane];
    float ss = xv.x * xv.x + xv.y * xv.y + xv.z * xv.z + xv.w * xv.w;
    #pragma unroll
    for (int o = 16; o; o >>= 1) ss += __shfl_xor_sync(0xffffffffu, ss, o);

    float norm = sqrtf(ss);
    float n    = fminf(fmaxf(norm, 1e-7f), 1.0f - 1e-7f);
    float fac  = atanhf(n) / n;
    float t0 = xv.x * fac, t1 = xv.y * fac, t2 = xv.z * fac, t3 = xv.w * fac;

    const float4 a1 = ((const float4*)a)[lane];
    const float4 a2 = ((const float4*)(a + 128))[lane];
    float w1 = t0 * a1.x + t1 * a1.y + t2 * a1.z + t3 * a1.w;
    float w2 = t0 * a2.x + t1 * a2.y + t2 * a2.z + t3 * a2.w;
    #pragma unroll
    for (int o = 16; o; o >>= 1) {
        w1 += __shfl_xor_sync(0xffffffffu, w1, o);
        w2 += __shfl_xor_sync(0xffffffffu, w2, o);
    }

    __half2* dst = (__half2*)(g_xt + (size_t)gw * 128);
    dst[lane * 2]     = __floats2half2_rn(t0, t1);
    dst[lane * 2 + 1] = __floats2half2_rn(t2, t3);

    if (lane == 0) {
        g_e1 [gw] = PSCALE * __expf(w1);
        g_e1p[gw] = PSCALE * __expf(0.2f * w1);
        g_e2 [gw] = __expf(w2);
        g_e2p[gw] = __expf(0.2f * w2);
    }
}

// ---------------- attention partial: prefetched adj stream + P-gen + HMMA ----------------
__global__ __launch_bounds__(512) void attn_kernel(const int* __restrict__ adj) {
    extern __shared__ char smem[];
    float* rs = (float*)(smem + SM_RS);

    const int tid = threadIdx.x;
    const int s   = blockIdx.x / NTILE;       // j-split index 0..2
    const int it  = blockIdx.x % NTILE;       // i-tile
    const int i0  = it * TILE;
    const int jtb = s * TPC;                  // first j-tile

    const int il = tid >> 2, jq = tid & 3;
    const int lane = tid & 31, wid = tid >> 5;
    const int wm = wid & 3, wn = wid >> 2;

    if (tid < TILE) rs[tid] = 0.f;
    __syncthreads();

    float acc[2][4][4];
    #pragma unroll
    for (int mt = 0; mt < 2; ++mt)
        #pragma unroll
        for (int nt = 0; nt < 4; ++nt)
            #pragma unroll
            for (int e = 0; e < 4; ++e) acc[mt][nt][e] = 0.f;

    const float e1  = g_e1 [i0 + il];
    const float e1p = g_e1p[i0 + il];
    const uint4* arow = (const uint4*)(adj + (size_t)(i0 + il) * N_TOK) + jq * 8;
    const uint32_t pbase = smem_u32(smem + SM_P);
    const uint32_t vbase = smem_u32(smem + SM_V);

    uint4 A[8];   // adj prefetch registers (one tile ahead)

    auto aload = [&](int jt) {
        const uint4* src = arow + jt * 32;
        #pragma unroll
        for (int c = 0; c < 8; ++c) A[c] = __ldcs(src + c);
    };
    auto vcopy = [&](int jt, int vb) {
        __half* Vm = (__half*)(smem + SM_V + vb * PVB);
        const uint4* vs = (const uint4*)(g_xt + (size_t)jt * TILE * 128);
        #pragma unroll
        for (int q = 0; q < 4; ++q) {
            int idx = q * 512 + tid;
            int r = idx >> 4, cc = idx & 15;
            *(uint4*)(Vm + r * PSTR + cc * 8) = __ldg(vs + idx);
        }
    };
    auto pgen = [&](int jt, int pb) {
        const float4* e2v  = (const float4*)(g_e2  + jt * TILE + jq * 32);
        const float4* e2pv = (const float4*)(g_e2p + jt * TILE + jq * 32);
        __half* Pm = (__half*)(smem + SM_P + pb * PVB);
        union { __half h[32]; uint4 u[4]; } pk;
        float psum = 0.f;
        #pragma unroll
        for (int c = 0; c < 8; ++c) {
            uint4  av  = A[c];
            float4 ev  = __ldg(e2v + c);
            float4 epv = __ldg(e2pv + c);
            float p0 = fmaxf(e1 * ev.x, e1p * epv.x);
            float p1 = fmaxf(e1 * ev.y, e1p * epv.y);
            float p2 = fmaxf(e1 * ev.z, e1p * epv.z);
            float p3 = fmaxf(e1 * ev.w, e1p * epv.w);
            p0 = av.x ? p0 : 0.f;  p1 = av.y ? p1 : 0.f;
            p2 = av.z ? p2 : 0.f;  p3 = av.w ? p3 : 0.f;
            psum += (p0 + p1) + (p2 + p3);
            pk.h[c * 4 + 0] = __float2half_rn(p0);
            pk.h[c * 4 + 1] = __float2half_rn(p1);
            pk.h[c * 4 + 2] = __float2half_rn(p2);
            pk.h[c * 4 + 3] = __float2half_rn(p3);
        }
        uint4* pd = (uint4*)(Pm + il * PSTR + jq * 32);
        #pragma unroll
        for (int q = 0; q < 4; ++q) pd[q] = pk.u[q];

        psum += __shfl_xor_sync(0xffffffffu, psum, 1);
        psum += __shfl_xor_sync(0xffffffffu, psum, 2);
        if (jq == 0) rs[il] += psum;
    };
    auto mma_tile = [&](int t) {
        const uint32_t pb = pbase + (t & 1) * PVB;
        const uint32_t vb = vbase + (t & 1) * PVB;
        #pragma unroll
        for (int k = 0; k < 8; ++k) {
            uint32_t afr[2][4], bfr[4][2];
            uint32_t aaddr = pb + (uint32_t)(((wm * 32 + (lane & 15)) * PSTR
                                     + k * 16 + (lane >> 4) * 8) * 2);
            ldsm_x4(aaddr,                 afr[0][0], afr[0][1], afr[0][2], afr[0][3]);
            ldsm_x4(aaddr + 16 * PSTR * 2, afr[1][0], afr[1][1], afr[1][2], afr[1][3]);

            uint32_t baddr = vb + (uint32_t)(((k * 16 + (lane & 15)) * PSTR
                                     + wn * 32 + (lane >> 4) * 8) * 2);
            ldsm_x4_t(baddr,      bfr[0][0], bfr[0][1], bfr[1][0], bfr[1][1]);
            ldsm_x4_t(baddr + 32, bfr[2][0], bfr[2][1], bfr[3][0], bfr[3][1]);

            #pragma unroll
            for (int mt = 0; mt < 2; ++mt)
                #pragma unroll
                for (int nt = 0; nt < 4; ++nt)
                    mma16816(acc[mt][nt], afr[mt], bfr[nt]);
        }
    };

    // ---- prologue: adj(tile0) -> regs, stage tile0 buffers ----
    aload(jtb);
    vcopy(jtb, 0);
    pgen(jtb, 0);          // consumes A(tile0)

    // ---- main loop: region = { aload(t+1) | vcopy(t+1) | MMA(t) | pgen(t+1) } ----
    #pragma unroll 1
    for (int t = 0; t < TPC; ++t) {
        __syncthreads();
        const bool more = (t + 1 < TPC);
        if (more) {
            aload(jtb + t + 1);        // LDGs issue here; consumed ~MMA-duration later
            vcopy(jtb + t + 1, (t + 1) & 1);
        }
        mma_tile(t);                   // long tensor/LDSM section hides adj latency
        if (more) pgen(jtb + t + 1, (t + 1) & 1);
    }

    // ---- write partials: raw acc + rowsum ----
    float* pc = g_pc + ((size_t)s * NTILE + it) * (TILE * 128);
    #pragma unroll
    for (int mt = 0; mt < 2; ++mt) {
        int rlo = wm * 32 + mt * 16 + (lane >> 2);
        int rhi = rlo + 8;
        #pragma unroll
        for (int nt = 0; nt < 4; ++nt) {
            int col = wn * 32 + nt * 8 + 2 * (lane & 3);
            *(float2*)(pc + (size_t)rlo * 128 + col) = make_float2(acc[mt][nt][0], acc[mt][nt][1]);
            *(float2*)(pc + (size_t)rhi * 128 + col) = make_float2(acc[mt][nt][2], acc[mt][nt][3]);
        }
    }
    if (tid < TILE) g_prs[(size_t)s * N_TOK + i0 + tid] = rs[tid];
}

// ---------------- combine: sum partials, /rowsum, expmap0 + proj ----------------
__global__ __launch_bounds__(256) void combine_kernel(float* __restrict__ out) {
    int gw   = (blockIdx.x * blockDim.x + threadIdx.x) >> 5;   // global row
    int lane = threadIdx.x & 31;
    if (gw >= N_TOK) return;

    const size_t roff = (size_t)gw * 128 + lane * 4;
    float4 c0 = *(const float4*)(g_pc + roff);
    float4 c1 = *(const float4*)(g_pc + (size_t)NTILE * TILE * 128 + roff);
    float4 c2 = *(const float4*)(g_pc + (size_t)2 * NTILE * TILE * 128 + roff);
    float rsum = g_prs[gw] + g_prs[N_TOK + gw] + g_prs[2 * N_TOK + gw];
    float inv = 1.f / rsum;

    float4 y;
    y.x = (c0.x + c1.x + c2.x) * inv;
    y.y = (c0.y + c1.y + c2.y) * inv;
    y.z = (c0.z + c1.z + c2.z) * inv;
    y.w = (c0.w + c1.w + c2.w) * inv;

    float ss = y.x * y.x + y.y * y.y + y.z * y.z + y.w * y.w;
    #pragma unroll
    for (int o = 16; o; o >>= 1) ss += __shfl_xor_sync(0xffffffffu, ss, o);

    float nn = fmaxf(sqrtf(ss), 1e-7f);
    float t  = tanhf(nn);
    float f  = ((t > 0.999f) ? 0.999f : t) / nn;

    y.x *= f; y.y *= f; y.z *= f; y.w *= f;
    *(float4*)(out + roff) = y;
}

// ---------------- launch ----------------
extern "C" void kernel_launch(void* const* d_in, const int* in_sizes, int n_in,
                              void* d_out, int out_size) {
    const float* x   = (const float*)d_in[0];
    const int*   adj = (const int*)d_in[1];
    const float* a   = (const float*)d_in[2];
    float*       out = (float*)d_out;

    cudaFuncSetAttribute(attn_kernel, cudaFuncAttributeMaxDynamicSharedMemorySize, SMEM_TOTAL);

    prep_kernel<<<N_TOK / 8, 256>>>(x, a);
    attn_kernel<<<NSPLIT * NTILE, 512, SMEM_TOTAL>>>(adj);
    combine_kernel<<<N_TOK / 8, 256>>>(out);
}

// round 11
// speedup vs baseline: 1.3253x; 1.3253x over previous
#include <cuda_runtime.h>
#include <cuda_fp16.h>
#include <cstdint>

#define N_TOK  12288
#define TILE_M 128
#define TILE_N 64          // j-tile width
#define NIT    96          // i-tiles
#define NJT    192         // j-tiles (N_TOK / TILE_N)
#define NSPLIT 3
#define TPC    64          // j-tiles per CTA (NJT / NSPLIT)
#define PSCALE 0.7f

#define PSTR_P 72          // halves per P row (144 B)
#define PSTR_V 136         // halves per V row (272 B)

// smem byte offsets
#define SM_ADJ  0          // 2 x 32768 (adj tiles; layout q*8192 + tid*16)
#define SM_V    65536      // 64 x 272 = 17408
#define SM_P    82944      // 128 x 144 = 18432
#define SM_RS   101376     // 128 floats
#define SMEM_TOTAL 101888

// ---------------- scratch (static device globals) ----------------
__device__ __half g_xt[(size_t)N_TOK * 128];            // x_tan fp16 [N, D]
__device__ float  g_e1[N_TOK];                          // 0.7*exp(wh1)
__device__ float  g_e1p[N_TOK];                         // 0.7*exp(0.2*wh1)
__device__ float  g_e2[N_TOK];                          // exp(wh2)
__device__ float  g_e2p[N_TOK];                         // exp(0.2*wh2)
__device__ float  g_pc[(size_t)NSPLIT * N_TOK * 128];   // partial C, 18.9 MB
__device__ float  g_prs[(size_t)NSPLIT * N_TOK];        // partial rowsums

// ---------------- PTX helpers ----------------
__device__ __forceinline__ uint32_t smem_u32(const void* p) {
    return (uint32_t)__cvta_generic_to_shared(p);
}
__device__ __forceinline__ void cp16(uint32_t dst, const void* src) {
    asm volatile("cp.async.cg.shared.global [%0], [%1], 16;" :: "r"(dst), "l"(src));
}
#define CP_COMMIT() asm volatile("cp.async.commit_group;" ::: "memory")
#define CP_WAIT(n)  asm volatile("cp.async.wait_group %0;" :: "n"(n) : "memory")
__device__ __forceinline__ void ldsm_x4(uint32_t addr, uint32_t& r0, uint32_t& r1,
                                        uint32_t& r2, uint32_t& r3) {
    asm volatile("ldmatrix.sync.aligned.m8n8.x4.shared.b16 {%0,%1,%2,%3}, [%4];"
                 : "=r"(r0), "=r"(r1), "=r"(r2), "=r"(r3) : "r"(addr));
}
__device__ __forceinline__ void ldsm_x4_t(uint32_t addr, uint32_t& r0, uint32_t& r1,
                                          uint32_t& r2, uint32_t& r3) {
    asm volatile("ldmatrix.sync.aligned.m8n8.x4.trans.shared.b16 {%0,%1,%2,%3}, [%4];"
                 : "=r"(r0), "=r"(r1), "=r"(r2), "=r"(r3) : "r"(addr));
}
__device__ __forceinline__ void mma16816(float* c, const uint32_t* a, const uint32_t* b) {
    asm volatile("mma.sync.aligned.m16n8k16.row.col.f32.f16.f16.f32 "
                 "{%0,%1,%2,%3}, {%4,%5,%6,%7}, {%8,%9}, {%0,%1,%2,%3};"
                 : "+f"(c[0]), "+f"(c[1]), "+f"(c[2]), "+f"(c[3])
                 : "r"(a[0]), "r"(a[1]), "r"(a[2]), "r"(a[3]), "r"(b[0]), "r"(b[1]));
}

// ---------------- prep: logmap0 + wh exp factors + fp16 x_tan ----------------
__global__ __launch_bounds__(256) void prep_kernel(const float* __restrict__ x,
                                                   const float* __restrict__ a) {
    int gw   = (blockIdx.x * blockDim.x + threadIdx.x) >> 5;
    int lane = threadIdx.x & 31;
    if (gw >= N_TOK) return;

    const float4 xv = ((const float4*)(x + (size_t)gw * 128))[lane];
    float ss = xv.x * xv.x + xv.y * xv.y + xv.z * xv.z + xv.w * xv.w;
    #pragma unroll
    for (int o = 16; o; o >>= 1) ss += __shfl_xor_sync(0xffffffffu, ss, o);

    float norm = sqrtf(ss);
    float n    = fminf(fmaxf(norm, 1e-7f), 1.0f - 1e-7f);
    float fac  = atanhf(n) / n;
    float t0 = xv.x * fac, t1 = xv.y * fac, t2 = xv.z * fac, t3 = xv.w * fac;

    const float4 a1 = ((const float4*)a)[lane];
    const float4 a2 = ((const float4*)(a + 128))[lane];
    float w1 = t0 * a1.x + t1 * a1.y + t2 * a1.z + t3 * a1.w;
    float w2 = t0 * a2.x + t1 * a2.y + t2 * a2.z + t3 * a2.w;
    #pragma unroll
    for (int o = 16; o; o >>= 1) {
        w1 += __shfl_xor_sync(0xffffffffu, w1, o);
        w2 += __shfl_xor_sync(0xffffffffu, w2, o);
    }

    __half2* dst = (__half2*)(g_xt + (size_t)gw * 128);
    dst[lane * 2]     = __floats2half2_rn(t0, t1);
    dst[lane * 2 + 1] = __floats2half2_rn(t2, t3);

    if (lane == 0) {
        g_e1 [gw] = PSCALE * __expf(w1);
        g_e1p[gw] = PSCALE * __expf(0.2f * w1);
        g_e2 [gw] = __expf(w2);
        g_e2p[gw] = __expf(0.2f * w2);
    }
}

// ---------------- attention partial: cp.async adj + P-gen + HMMA, 2 CTAs/SM ----------------
__global__ __launch_bounds__(512, 2) void attn_kernel(const int* __restrict__ adj) {
    extern __shared__ char smem[];
    float* rs = (float*)(smem + SM_RS);

    const int tid = threadIdx.x;
    const int s   = blockIdx.x / NIT;         // j-split 0..2
    const int it  = blockIdx.x % NIT;         // i-tile
    const int i0  = it * TILE_M;
    const int jtb = s * TPC;                  // first j-tile

    const int il = tid >> 2, jq = tid & 3;    // pgen mapping: row il, 16-col slice jq
    const int lane = tid & 31, wid = tid >> 5;
    const int wm = wid & 3, wn = wid >> 2;

    if (tid < TILE_M) rs[tid] = 0.f;
    __syncthreads();

    float acc[2][4][4];
    #pragma unroll
    for (int mt = 0; mt < 2; ++mt)
        #pragma unroll
        for (int nt = 0; nt < 4; ++nt)
            #pragma unroll
            for (int e = 0; e < 4; ++e) acc[mt][nt][e] = 0.f;

    const float e1  = g_e1 [i0 + il];
    const float e1p = g_e1p[i0 + il];
    // this thread's 64B adj slice base (row i0+il, cols jt*64 + jq*16 ..)
    const int* agbase = adj + (size_t)(i0 + il) * N_TOK + jq * 16;
    const uint32_t smb   = smem_u32(smem);
    const uint32_t pbase = smb + SM_P;
    const uint32_t vbase = smb + SM_V;

    auto adj_cp = [&](int jt, int ab) {   // self-owned 64B: 4 x cp.async 16B
        const int* src = agbase + jt * TILE_N;
        uint32_t dst = smb + SM_ADJ + ab * 32768 + tid * 16;
        #pragma unroll
        for (int q = 0; q < 4; ++q) cp16(dst + q * 8192, src + q * 4);
    };
    auto v_cp = [&](int jt) {             // V tile (64 rows x 128 d fp16), coalesced
        const __half* src = g_xt + (size_t)jt * TILE_N * 128;
        #pragma unroll
        for (int q = 0; q < 2; ++q) {
            int idx = q * 512 + tid;       // chunk id over 64 rows x 16 chunks
            int r = idx >> 4, ch = idx & 15;
            cp16(vbase + r * (PSTR_V * 2) + ch * 16, src + (size_t)r * 128 + ch * 8);
        }
    };
    auto pgen = [&](int jt, int ab) {
        const int j0 = jt * TILE_N;
        const float4* e2v  = (const float4*)(g_e2  + j0 + jq * 16);
        const float4* e2pv = (const float4*)(g_e2p + j0 + jq * 16);
        union { __half h[16]; uint4 u4[2]; } pk;
        float psum = 0.f;
        #pragma unroll
        for (int q = 0; q < 4; ++q) {
            uint4 av = *(const uint4*)(smem + SM_ADJ + ab * 32768 + q * 8192 + tid * 16);
            float4 ev  = __ldg(e2v + q);
            float4 epv = __ldg(e2pv + q);
            float p0 = fmaxf(e1 * ev.x, e1p * epv.x);
            float p1 = fmaxf(e1 * ev.y, e1p * epv.y);
            float p2 = fmaxf(e1 * ev.z, e1p * epv.z);
            float p3 = fmaxf(e1 * ev.w, e1p * epv.w);
            p0 = av.x ? p0 : 0.f;  p1 = av.y ? p1 : 0.f;
            p2 = av.z ? p2 : 0.f;  p3 = av.w ? p3 : 0.f;
            psum += (p0 + p1) + (p2 + p3);
            pk.h[q * 4 + 0] = __float2half_rn(p0);
            pk.h[q * 4 + 1] = __float2half_rn(p1);
            pk.h[q * 4 + 2] = __float2half_rn(p2);
            pk.h[q * 4 + 3] = __float2half_rn(p3);
        }
        uint4* pd = (uint4*)(smem + SM_P + il * (PSTR_P * 2) + jq * 32);
        pd[0] = pk.u4[0];
        pd[1] = pk.u4[1];
        psum += __shfl_xor_sync(0xffffffffu, psum, 1);
        psum += __shfl_xor_sync(0xffffffffu, psum, 2);
        if (jq == 0) rs[il] += psum;
    };

    // ---- prologue: adj(tile 0) in flight ----
    adj_cp(jtb, 0);
    CP_COMMIT();

    #pragma unroll 1
    for (int t = 0; t < TPC; ++t) {
        const int ab = t & 1;
        // (a) V(t) async (L2-resident)
        v_cp(jtb + t);
        CP_COMMIT();
        // (b) adj(t) ready (oldest group)
        CP_WAIT(1);
        // (c) P-gen(t): consumes own adj bytes, writes P + rowsum
        pgen(jtb + t, ab);
        // (d) adj(t+1) async — a full iteration of slack
        if (t + 1 < TPC) { adj_cp(jtb + t + 1, ab ^ 1); CP_COMMIT(); CP_WAIT(1); }
        else             { CP_WAIT(0); }
        // (e->f) V(t) complete; make P/V visible to all warps
        __syncthreads();
        // (g) MMA(t): C[128x128] += P[128x64] * V[64x128]
        #pragma unroll
        for (int k = 0; k < 4; ++k) {
            uint32_t afr[2][4], bfr[4][2];
            uint32_t aaddr = pbase + (uint32_t)((wm * 32 + (lane & 15)) * (PSTR_P * 2)
                                     + (k * 16 + (lane >> 4) * 8) * 2);
            ldsm_x4(aaddr,                       afr[0][0], afr[0][1], afr[0][2], afr[0][3]);
            ldsm_x4(aaddr + 16 * (PSTR_P * 2),   afr[1][0], afr[1][1], afr[1][2], afr[1][3]);

            uint32_t baddr = vbase + (uint32_t)((k * 16 + (lane & 15)) * (PSTR_V * 2)
                                     + (wn * 32 + (lane >> 4) * 8) * 2);
            ldsm_x4_t(baddr,      bfr[0][0], bfr[0][1], bfr[1][0], bfr[1][1]);
            ldsm_x4_t(baddr + 32, bfr[2][0], bfr[2][1], bfr[3][0], bfr[3][1]);

            #pragma unroll
            for (int mt = 0; mt < 2; ++mt)
                #pragma unroll
                for (int nt = 0; nt < 4; ++nt)
                    mma16816(acc[mt][nt], afr[mt], bfr[nt]);
        }
        // (h) protect single-buffered P/V before next iteration overwrites
        __syncthreads();
    }

    // ---- write partials: raw acc + rowsum ----
    float* pc = g_pc + ((size_t)s * NIT + it) * (TILE_M * 128);
    #pragma unroll
    for (int mt = 0; mt < 2; ++mt) {
        int rlo = wm * 32 + mt * 16 + (lane >> 2);
        int rhi = rlo + 8;
        #pragma unroll
        for (int nt = 0; nt < 4; ++nt) {
            int col = wn * 32 + nt * 8 + 2 * (lane & 3);
            *(float2*)(pc + (size_t)rlo * 128 + col) = make_float2(acc[mt][nt][0], acc[mt][nt][1]);
            *(float2*)(pc + (size_t)rhi * 128 + col) = make_float2(acc[mt][nt][2], acc[mt][nt][3]);
        }
    }
    if (tid < TILE_M) g_prs[(size_t)s * N_TOK + i0 + tid] = rs[tid];
}

// ---------------- combine: sum partials, /rowsum, expmap0 + proj ----------------
__global__ __launch_bounds__(256) void combine_kernel(float* __restrict__ out) {
    int gw   = (blockIdx.x * blockDim.x + threadIdx.x) >> 5;   // global row
    int lane = threadIdx.x & 31;
    if (gw >= N_TOK) return;

    const size_t roff = (size_t)gw * 128 + lane * 4;
    float4 c0 = *(const float4*)(g_pc + roff);
    float4 c1 = *(const float4*)(g_pc + (size_t)N_TOK * 128 + roff);
    float4 c2 = *(const float4*)(g_pc + (size_t)2 * N_TOK * 128 + roff);
    float rsum = g_prs[gw] + g_prs[N_TOK + gw] + g_prs[2 * N_TOK + gw];
    float inv = 1.f / rsum;

    float4 y;
    y.x = (c0.x + c1.x + c2.x) * inv;
    y.y = (c0.y + c1.y + c2.y) * inv;
    y.z = (c0.z + c1.z + c2.z) * inv;
    y.w = (c0.w + c1.w + c2.w) * inv;

    float ss = y.x * y.x + y.y * y.y + y.z * y.z + y.w * y.w;
    #pragma unroll
    for (int o = 16; o; o >>= 1) ss += __shfl_xor_sync(0xffffffffu, ss, o);

    float nn = fmaxf(sqrtf(ss), 1e-7f);
    float t  = tanhf(nn);
    float f  = ((t > 0.999f) ? 0.999f : t) / nn;

    y.x *= f; y.y *= f; y.z *= f; y.w *= f;
    *(float4*)(out + roff) = y;
}

// ---------------- launch ----------------
extern "C" void kernel_launch(void* const* d_in, const int* in_sizes, int n_in,
                              void* d_out, int out_size) {
    const float* x   = (const float*)d_in[0];
    const int*   adj = (const int*)d_in[1];
    const float* a   = (const float*)d_in[2];
    float*       out = (float*)d_out;

    cudaFuncSetAttribute(attn_kernel, cudaFuncAttributeMaxDynamicSharedMemorySize, SMEM_TOTAL);

    prep_kernel<<<N_TOK / 8, 256>>>(x, a);
    attn_kernel<<<NSPLIT * NIT, 512, SMEM_TOTAL>>>(adj);
    combine_kernel<<<N_TOK / 8, 256>>>(out);
}